// round 1
// baseline (speedup 1.0000x reference)
#include <cuda_runtime.h>
#include <math.h>
#include <float.h>

// ---------------------------------------------------------------------------
// Problem constants (fixed by the dataset)
// ---------------------------------------------------------------------------
#define NMAX 50048
#define EMAX 1600000
#define GMAXC 64

// ---------------------------------------------------------------------------
// Scratch (static device globals; no allocation at runtime)
// ---------------------------------------------------------------------------
__device__ float g_deg[NMAX];
__device__ float g_dinv[NMAX];
__device__ int   g_cnt[NMAX];
__device__ int   g_fill[NMAX];
__device__ int   g_rowstart[NMAX + 1];
__device__ int   g_ecol[EMAX];
__device__ float g_enorm[EMAX];
__device__ float g_Z [NMAX * 256];
__device__ float g_T1[NMAX * 256];
__device__ float g_T2[NMAX * 256];
__device__ float g_H [NMAX * 256];
__device__ float g_bnsum[256];
__device__ float g_bnsq [256];
__device__ float g_scale[256];
__device__ float g_shift[256];
__device__ int   g_poolmax[GMAXC * 256];
__device__ float g_poolsum[GMAXC * 256];
__device__ int   g_segstart[GMAXC + 1];

// ---------------------------------------------------------------------------
// Helpers
// ---------------------------------------------------------------------------
__device__ __forceinline__ float softplus_f(float x) {
    // log1p(exp(x)), numerically stable
    return fmaxf(x, 0.f) + log1pf(expf(-fabsf(x)));
}

// monotone float <-> int map for atomicMax on signed int
__device__ __forceinline__ int fmap_f(float f) {
    int i = __float_as_int(f);
    return (i < 0) ? (i ^ 0x7FFFFFFF) : i;
}
__device__ __forceinline__ float funmap_f(int k) {
    return __int_as_float((k < 0) ? (k ^ 0x7FFFFFFF) : k);
}

// ---------------------------------------------------------------------------
// Preprocessing kernels
// ---------------------------------------------------------------------------
__global__ void zero_init_k(int n) {
    int i = blockIdx.x * blockDim.x + threadIdx.x;
    if (i < n) { g_deg[i] = 0.f; g_cnt[i] = 0; g_fill[i] = 0; }
}

__global__ void edge_deg_k(const int* __restrict__ ei, const float* __restrict__ ew, int E) {
    int e = blockIdx.x * blockDim.x + threadIdx.x;
    if (e >= E) return;
    int r = ei[e];
    atomicAdd(&g_deg[r], ew[e]);
    atomicAdd(&g_cnt[r], 1);
}

__global__ void dinv_k(int n) {
    int i = blockIdx.x * blockDim.x + threadIdx.x;
    if (i >= n) return;
    float d = g_deg[i];
    g_dinv[i] = (d > 0.f) ? rsqrtf(d) : 0.f;
}

__global__ void scan_k(int n) {
    __shared__ int wsum[32];
    __shared__ int carry_s;
    int tid = threadIdx.x, lane = tid & 31, wid = tid >> 5;
    if (tid == 0) carry_s = 0;
    __syncthreads();
    for (int base = 0; base < n; base += 1024) {
        int i = base + tid;
        int v = (i < n) ? g_cnt[i] : 0;
        int x = v;
#pragma unroll
        for (int off = 1; off < 32; off <<= 1) {
            int t = __shfl_up_sync(0xffffffffu, x, off);
            if (lane >= off) x += t;
        }
        if (lane == 31) wsum[wid] = x;
        __syncthreads();
        if (wid == 0) {
            int y = wsum[lane];
#pragma unroll
            for (int off = 1; off < 32; off <<= 1) {
                int t = __shfl_up_sync(0xffffffffu, y, off);
                if (lane >= off) y += t;
            }
            wsum[lane] = y;
        }
        __syncthreads();
        int pre   = (wid > 0) ? wsum[wid - 1] : 0;
        int carry = carry_s;
        int incl  = x + pre + carry;
        if (i < n) g_rowstart[i] = incl - v;   // exclusive
        __syncthreads();
        if (tid == 1023) carry_s = incl;
        __syncthreads();
    }
    if (tid == 0) g_rowstart[n] = carry_s;
}

__global__ void edge_fill_k(const int* __restrict__ ei, const float* __restrict__ ew, int E) {
    int e = blockIdx.x * blockDim.x + threadIdx.x;
    if (e >= E) return;
    int r = ei[e];
    int c = ei[E + e];
    int p = g_rowstart[r] + atomicAdd(&g_fill[r], 1);
    g_ecol[p]  = c;
    g_enorm[p] = -ew[e] * g_dinv[r] * g_dinv[c];
}

// ---------------------------------------------------------------------------
// Sparse propagation: out[row] = sum_{edges of row} norm * z[col]
// blockDim = (fi/4, 128/(fi/4)); one (row, 4-feature-group) per thread
// insel: 0 = external pointer, 1 = g_Z, 2 = g_T1.  outsel: 1 = g_T1, 2 = g_T2.
// ---------------------------------------------------------------------------
__global__ void prop_k(const float* __restrict__ Xext, int insel, int outsel, int n, int fi4) {
    int row = blockIdx.x * blockDim.y + threadIdx.y;
    if (row >= n) return;
    const float* Zin = (insel == 0) ? Xext : ((insel == 1) ? g_Z : g_T1);
    float* Out       = (outsel == 1) ? g_T1 : g_T2;
    int xf = threadIdx.x;
    int s = g_rowstart[row], e = g_rowstart[row + 1];
    const float4* Z4 = (const float4*)Zin;
    float ax = 0.f, ay = 0.f, az = 0.f, aw = 0.f;
    int i = s;
    for (; i + 2 <= e; i += 2) {
        int   c0 = g_ecol[i],   c1 = g_ecol[i + 1];
        float w0 = g_enorm[i],  w1 = g_enorm[i + 1];
        float4 z0 = Z4[c0 * fi4 + xf];
        float4 z1 = Z4[c1 * fi4 + xf];
        ax = fmaf(w0, z0.x, ax); ay = fmaf(w0, z0.y, ay);
        az = fmaf(w0, z0.z, az); aw = fmaf(w0, z0.w, aw);
        ax = fmaf(w1, z1.x, ax); ay = fmaf(w1, z1.y, ay);
        az = fmaf(w1, z1.z, az); aw = fmaf(w1, z1.w, aw);
    }
    if (i < e) {
        int   c0 = g_ecol[i];
        float w0 = g_enorm[i];
        float4 z0 = Z4[c0 * fi4 + xf];
        ax = fmaf(w0, z0.x, ax); ay = fmaf(w0, z0.y, ay);
        az = fmaf(w0, z0.z, az); aw = fmaf(w0, z0.w, aw);
    }
    float4 o; o.x = ax; o.y = ay; o.z = az; o.w = aw;
    ((float4*)Out)[row * fi4 + xf] = o;
}

// ---------------------------------------------------------------------------
// Chebyshev combine GEMM:
//   H = Z @ W0 + T1 @ W1 + (2*T2raw - Z) @ W2 + b     (+ optional softplus)
// Register-tiled SIMT: each thread -> RM rows x 4 cols (float4).
// ---------------------------------------------------------------------------
template<int FI, int FO, bool ACT>
__global__ __launch_bounds__(128) void cheb_gemm_k(
    const float* __restrict__ Xext, const float* __restrict__ W,
    const float* __restrict__ b, int n)
{
    constexpr int CG  = FO / 4;        // column groups of 4
    constexpr int RPI = 128 / CG;      // row stride between a thread's rows
    constexpr int RM  = 4;             // rows per thread
    constexpr int BM  = RPI * RM;      // rows per block

    const float* Z   = Xext ? Xext : g_Z;
    const float* T1  = g_T1;
    const float* T2r = g_T2;
    float*       H   = g_H;

    const int cg = threadIdx.x % CG;
    const int r0 = threadIdx.x / CG;
    const int rowbase = blockIdx.x * BM;

    const float4* W4 = (const float4*)W;   // [3][FI][CG] of float4
    float acc[RM][4];
    float4 bb = ((const float4*)b)[cg];
    int  rows[RM];
    bool vld[RM];
#pragma unroll
    for (int r = 0; r < RM; r++) {
        acc[r][0] = bb.x; acc[r][1] = bb.y; acc[r][2] = bb.z; acc[r][3] = bb.w;
        rows[r] = rowbase + r0 + r * RPI;
        vld[r]  = rows[r] < n;
    }

#pragma unroll 2
    for (int k0 = 0; k0 < FI; k0 += 4) {
        float zs[RM][4], t1s[RM][4], t2s[RM][4];
#pragma unroll
        for (int r = 0; r < RM; r++) {
            float4 z4 = make_float4(0.f, 0.f, 0.f, 0.f);
            float4 a4 = z4, p4 = z4;
            if (vld[r]) {
                int off = rows[r] * (FI / 4) + (k0 >> 2);
                z4 = ((const float4*)Z)[off];
                a4 = ((const float4*)T1)[off];
                p4 = ((const float4*)T2r)[off];
            }
            zs[r][0] = z4.x; zs[r][1] = z4.y; zs[r][2] = z4.z; zs[r][3] = z4.w;
            t1s[r][0] = a4.x; t1s[r][1] = a4.y; t1s[r][2] = a4.z; t1s[r][3] = a4.w;
            t2s[r][0] = 2.f * p4.x - z4.x;
            t2s[r][1] = 2.f * p4.y - z4.y;
            t2s[r][2] = 2.f * p4.z - z4.z;
            t2s[r][3] = 2.f * p4.w - z4.w;
        }
#pragma unroll
        for (int kk = 0; kk < 4; kk++) {
            float4 w0 = W4[(k0 + kk) * CG + cg];
            float4 w1 = W4[FI * CG + (k0 + kk) * CG + cg];
            float4 w2 = W4[2 * FI * CG + (k0 + kk) * CG + cg];
#pragma unroll
            for (int r = 0; r < RM; r++) {
                float a = zs[r][kk], t = t1s[r][kk], u = t2s[r][kk];
                acc[r][0] = fmaf(a, w0.x, acc[r][0]);
                acc[r][1] = fmaf(a, w0.y, acc[r][1]);
                acc[r][2] = fmaf(a, w0.z, acc[r][2]);
                acc[r][3] = fmaf(a, w0.w, acc[r][3]);
                acc[r][0] = fmaf(t, w1.x, acc[r][0]);
                acc[r][1] = fmaf(t, w1.y, acc[r][1]);
                acc[r][2] = fmaf(t, w1.z, acc[r][2]);
                acc[r][3] = fmaf(t, w1.w, acc[r][3]);
                acc[r][0] = fmaf(u, w2.x, acc[r][0]);
                acc[r][1] = fmaf(u, w2.y, acc[r][1]);
                acc[r][2] = fmaf(u, w2.z, acc[r][2]);
                acc[r][3] = fmaf(u, w2.w, acc[r][3]);
            }
        }
    }

#pragma unroll
    for (int r = 0; r < RM; r++) {
        if (!vld[r]) continue;
        float4 o;
        if (ACT) {
            o.x = softplus_f(acc[r][0]); o.y = softplus_f(acc[r][1]);
            o.z = softplus_f(acc[r][2]); o.w = softplus_f(acc[r][3]);
        } else {
            o.x = acc[r][0]; o.y = acc[r][1]; o.z = acc[r][2]; o.w = acc[r][3];
        }
        ((float4*)H)[rows[r] * CG + cg] = o;
    }
}

// ---------------------------------------------------------------------------
// BatchNorm (training-mode, biased variance): stats + finalize + apply
// ---------------------------------------------------------------------------
__global__ void zero_bn_k() {
    int t = threadIdx.x;
    g_bnsum[t] = 0.f; g_bnsq[t] = 0.f;
}

__global__ void bn_stats_k(int n, int fo) {
    int tid = threadIdx.x;
    int f = tid % fo;
    int copy = tid / fo;
    int copies = 256 / fo;
    float s = 0.f, q = 0.f;
    for (int row = blockIdx.x * copies + copy; row < n; row += gridDim.x * copies) {
        float v = g_H[row * fo + f];
        s += v; q = fmaf(v, v, q);
    }
    __shared__ float sh[256], sh2[256];
    sh[tid] = s; sh2[tid] = q;
    __syncthreads();
    for (int off = 128; off >= fo; off >>= 1) {
        if (tid < off) { sh[tid] += sh[tid + off]; sh2[tid] += sh2[tid + off]; }
        __syncthreads();
    }
    if (tid < fo) {
        atomicAdd(&g_bnsum[tid], sh[tid]);
        atomicAdd(&g_bnsq [tid], sh2[tid]);
    }
}

__global__ void bn_finalize_k(const float* __restrict__ gma, const float* __restrict__ beta,
                              int n, int fo) {
    int f = threadIdx.x;
    if (f >= fo) return;
    float inv_n = 1.f / (float)n;
    float m = g_bnsum[f] * inv_n;
    float v = g_bnsq[f] * inv_n - m * m;
    float sc = gma[f] * rsqrtf(fmaxf(v, 0.f) + 1e-5f);
    g_scale[f] = sc;
    g_shift[f] = beta[f] - m * sc;
}

__global__ void bn_apply_k(int total4, int fo4) {
    for (int i = blockIdx.x * blockDim.x + threadIdx.x; i < total4;
         i += gridDim.x * blockDim.x) {
        float4 h  = ((const float4*)g_H)[i];
        int f4 = i % fo4;
        float4 sc = ((const float4*)g_scale)[f4];
        float4 sh = ((const float4*)g_shift)[f4];
        float4 o;
        o.x = fmaf(h.x, sc.x, sh.x);
        o.y = fmaf(h.y, sc.y, sh.y);
        o.z = fmaf(h.z, sc.z, sh.z);
        o.w = fmaf(h.w, sc.w, sh.w);
        ((float4*)g_Z)[i] = o;
    }
}

// ---------------------------------------------------------------------------
// Pooling (segment max + mean over sorted batch_index) and dense head
// ---------------------------------------------------------------------------
__global__ void segbounds_k(const int* __restrict__ batch, int n, int G) {
    int g = threadIdx.x;
    if (g > G) return;
    if (g == G) { g_segstart[G] = n; return; }
    int lo = 0, hi = n;
    while (lo < hi) {
        int mid = (lo + hi) >> 1;
        if (batch[mid] < g) lo = mid + 1; else hi = mid;
    }
    g_segstart[g] = lo;
}

__global__ void pool_init_k(int G) {
    int i = blockIdx.x * blockDim.x + threadIdx.x;
    if (i < G * 256) { g_poolmax[i] = INT_MIN; g_poolsum[i] = 0.f; }
}

#define POOL_ROWS 128
__global__ void pool_k(const int* __restrict__ batch, int n) {
    int f  = threadIdx.x;               // 256 features
    int rs = blockIdx.x * POOL_ROWS;
    if (rs >= n) return;
    int re = min(rs + POOL_ROWS, n);
    int cur = batch[rs];
    float mx = -FLT_MAX, sm = 0.f;
    for (int r = rs; r < re; r++) {
        int g = batch[r];
        if (g != cur) {
            atomicMax(&g_poolmax[cur * 256 + f], fmap_f(mx));
            atomicAdd(&g_poolsum[cur * 256 + f], sm);
            cur = g; mx = -FLT_MAX; sm = 0.f;
        }
        float v = g_H[r * 256 + f];
        mx = fmaxf(mx, v); sm += v;
    }
    atomicMax(&g_poolmax[cur * 256 + f], fmap_f(mx));
    atomicAdd(&g_poolsum[cur * 256 + f], sm);
}

__global__ void dense_k(const float* __restrict__ Wd, const float* __restrict__ bd,
                        float* __restrict__ out) {
    __shared__ float sh[4][128];
    int g = blockIdx.x, tid = threadIdx.x;
    int s = g_segstart[g], e = g_segstart[g + 1];
    float cnt = fmaxf((float)(e - s), 1.f);
    float a[4] = {0.f, 0.f, 0.f, 0.f};
    for (int k = tid; k < 512; k += 128) {
        float pv;
        if (k < 256) {
            int key = g_poolmax[g * 256 + k];
            pv = (key == INT_MIN) ? 0.f : funmap_f(key);
        } else {
            pv = g_poolsum[g * 256 + (k - 256)] / cnt;
        }
#pragma unroll
        for (int j = 0; j < 4; j++) a[j] = fmaf(pv, Wd[k * 4 + j], a[j]);
    }
#pragma unroll
    for (int j = 0; j < 4; j++) sh[j][tid] = a[j];
    __syncthreads();
    for (int off = 64; off >= 1; off >>= 1) {
        if (tid < off) {
#pragma unroll
            for (int j = 0; j < 4; j++) sh[j][tid] += sh[j][tid + off];
        }
        __syncthreads();
    }
    if (tid == 0) {
        float l[4];
#pragma unroll
        for (int j = 0; j < 4; j++) l[j] = sh[j][0] + bd[j];
        float m = fmaxf(fmaxf(l[0], l[1]), fmaxf(l[2], l[3]));
        float se = 0.f;
#pragma unroll
        for (int j = 0; j < 4; j++) se += expf(l[j] - m);
        float lse = m + logf(se);
#pragma unroll
        for (int j = 0; j < 4; j++) out[g * 4 + j] = l[j] - lse;
    }
}

// ---------------------------------------------------------------------------
// Host launcher
// ---------------------------------------------------------------------------
extern "C" void kernel_launch(void* const* d_in, const int* in_sizes, int n_in,
                              void* d_out, int out_size) {
    const float *x, *ew, *W[5], *b[5], *gm[4], *be[4], *Wd, *bd;
    const int *ei, *bi;

    // Disambiguate input ordering by size: setup-order has edge_index (3.2M) at slot 2,
    // reference-signature-order has W1 (6144) there.
    bool setup_order = (in_sizes[2] > 1000000);
    if (setup_order) {
        x  = (const float*)d_in[0];
        ew = (const float*)d_in[1];
        ei = (const int*)  d_in[2];
        bi = (const int*)  d_in[3];
        int p = 4;
        for (int l = 0; l < 5; l++) {
            W[l] = (const float*)d_in[p++];
            b[l] = (const float*)d_in[p++];
            if (l < 4) { gm[l] = (const float*)d_in[p++]; be[l] = (const float*)d_in[p++]; }
        }
        Wd = (const float*)d_in[p++];
        bd = (const float*)d_in[p++];
    } else {
        x  = (const float*)d_in[0];
        ew = (const float*)d_in[1];
        int p = 2;
        for (int l = 0; l < 5; l++) {
            W[l] = (const float*)d_in[p++];
            b[l] = (const float*)d_in[p++];
            if (l < 4) { gm[l] = (const float*)d_in[p++]; be[l] = (const float*)d_in[p++]; }
        }
        Wd = (const float*)d_in[p++];
        bd = (const float*)d_in[p++];
        ei = (const int*)d_in[p++];
        bi = (const int*)d_in[p++];
    }

    const int n = in_sizes[0] / 128;
    const int E = in_sizes[1];
    const int G = out_size / 4;     // 64
    float* out = (float*)d_out;

    const int fi_arr[5] = {128, 16, 32, 64, 128};

    // ---- preprocessing: degrees, dinv, CSR build ----
    zero_init_k<<<(n + 255) / 256, 256>>>(n);
    edge_deg_k<<<(E + 255) / 256, 256>>>(ei, ew, E);
    dinv_k<<<(n + 255) / 256, 256>>>(n);
    scan_k<<<1, 1024>>>(n);
    edge_fill_k<<<(E + 255) / 256, 256>>>(ei, ew, E);

    // ---- 5 Chebyshev layers ----
    for (int l = 0; l < 5; l++) {
        const int fi  = fi_arr[l];
        const int fi4 = fi / 4;
        const int insel = (l == 0) ? 0 : 1;     // layer 0 reads x, others read g_Z
        dim3 pblk(fi4, 128 / fi4);
        int  pgrd = (n + pblk.y - 1) / pblk.y;
        // T1 = L z
        prop_k<<<pgrd, pblk>>>(x, insel, 1, n, fi4);
        // T2raw = L T1  (t2 = 2*T2raw - z computed inside the GEMM)
        prop_k<<<pgrd, pblk>>>(x, 2, 2, n, fi4);

        switch (l) {
            case 0: cheb_gemm_k<128,  16, true ><<<(n + 127) / 128, 128>>>(x,       W[0], b[0], n); break;
            case 1: cheb_gemm_k< 16,  32, true ><<<(n +  63) /  64, 128>>>(nullptr, W[1], b[1], n); break;
            case 2: cheb_gemm_k< 32,  64, true ><<<(n +  31) /  32, 128>>>(nullptr, W[2], b[2], n); break;
            case 3: cheb_gemm_k< 64, 128, true ><<<(n +  15) /  16, 128>>>(nullptr, W[3], b[3], n); break;
            case 4: cheb_gemm_k<128, 256, false><<<(n +   7) /   8, 128>>>(nullptr, W[4], b[4], n); break;
        }

        if (l < 4) {
            const int fo = fi_arr[l + 1] == 0 ? 0 : 0; (void)fo;
            const int FO = (l == 0) ? 16 : (l == 1) ? 32 : (l == 2) ? 64 : 128;
            zero_bn_k<<<1, 256>>>();
            bn_stats_k<<<256, 256>>>(n, FO);
            bn_finalize_k<<<1, 256>>>(gm[l], be[l], n, FO);
            int total4 = n * FO / 4;
            int agrid = (total4 + 255) / 256;
            if (agrid > 2048) agrid = 2048;
            bn_apply_k<<<agrid, 256>>>(total4, FO / 4);
        }
    }

    // ---- pooling + dense head ----
    segbounds_k<<<1, 128>>>(bi, n, G);
    pool_init_k<<<(G * 256 + 255) / 256, 256>>>(G);
    pool_k<<<(n + POOL_ROWS - 1) / POOL_ROWS, 256>>>(bi, n);
    dense_k<<<G, 128>>>(Wd, bd, out);
}

// round 2
// speedup vs baseline: 1.0000x; 1.0000x over previous
#include <cuda_runtime.h>
#include <math.h>
#include <float.h>

// ---------------------------------------------------------------------------
// Problem constants (fixed by the dataset)
// ---------------------------------------------------------------------------
#define NMAX 50048
#define EMAX 1600000
#define GMAXC 64

typedef unsigned long long ull;

// ---------------------------------------------------------------------------
// Scratch (static device globals; no allocation at runtime)
// ---------------------------------------------------------------------------
__device__ float g_deg[NMAX];
__device__ float g_dinv[NMAX];
__device__ int   g_cnt[NMAX];
__device__ int   g_fill[NMAX];
__device__ int   g_rowstart[NMAX];
__device__ int   g_total;
__device__ int2  g_epack[EMAX];
__device__ float g_Z [NMAX * 256];
__device__ float g_T1[NMAX * 256];
__device__ float g_T2[NMAX * 256];
__device__ float g_H [NMAX * 256];
__device__ float g_bnsum[256];
__device__ float g_bnsq [256];
__device__ float g_scale[256];
__device__ float g_shift[256];
__device__ int   g_poolmax[GMAXC * 256];
__device__ float g_poolsum[GMAXC * 256];
__device__ int   g_segstart[GMAXC + 1];

// ---------------------------------------------------------------------------
// Helpers
// ---------------------------------------------------------------------------
__device__ __forceinline__ float softplus_f(float x) {
    return fmaxf(x, 0.f) + log1pf(expf(-fabsf(x)));
}

__device__ __forceinline__ int fmap_f(float f) {
    int i = __float_as_int(f);
    return (i < 0) ? (i ^ 0x7FFFFFFF) : i;
}
__device__ __forceinline__ float funmap_f(int k) {
    return __int_as_float((k < 0) ? (k ^ 0x7FFFFFFF) : k);
}

// packed fp32x2 FMA (Blackwell): d = a*b + d per 32-bit lane
__device__ __forceinline__ void fma2(ull &d, ull a, ull b) {
    asm("fma.rn.f32x2 %0, %1, %2, %0;" : "+l"(d) : "l"(a), "l"(b));
}
__device__ __forceinline__ ull bc2(float a) {
    ull r; unsigned int u = __float_as_uint(a);
    asm("mov.b64 %0, {%1, %1};" : "=l"(r) : "r"(u));
    return r;
}
union F2U { ull u; float2 f; };

// ---------------------------------------------------------------------------
// Preprocessing kernels
// ---------------------------------------------------------------------------
__global__ void zero_init_k(int n) {
    int i = blockIdx.x * blockDim.x + threadIdx.x;
    if (i < n) { g_deg[i] = 0.f; g_cnt[i] = 0; g_fill[i] = 0; }
    if (i == 0) g_total = 0;
}

__global__ void edge_deg_k(const int* __restrict__ ei, const float* __restrict__ ew, int E) {
    int e = blockIdx.x * blockDim.x + threadIdx.x;
    if (e >= E) return;
    int r = ei[e];
    atomicAdd(&g_deg[r], ew[e]);
    atomicAdd(&g_cnt[r], 1);
}

__global__ void dinv_k(int n) {
    int i = blockIdx.x * blockDim.x + threadIdx.x;
    if (i >= n) return;
    float d = g_deg[i];
    g_dinv[i] = (d > 0.f) ? rsqrtf(d) : 0.f;
}

// per-block scan + one global atomic per block (replaces serial scan)
__global__ void rowbase_k(int n) {
    __shared__ int wsum[32];
    __shared__ int blockbase;
    int tid = threadIdx.x, lane = tid & 31, wid = tid >> 5;
    int i = blockIdx.x * 1024 + tid;
    int v = (i < n) ? g_cnt[i] : 0;
    int x = v;
#pragma unroll
    for (int off = 1; off < 32; off <<= 1) {
        int t = __shfl_up_sync(0xffffffffu, x, off);
        if (lane >= off) x += t;
    }
    if (lane == 31) wsum[wid] = x;
    __syncthreads();
    if (wid == 0) {
        int y = wsum[lane];
#pragma unroll
        for (int off = 1; off < 32; off <<= 1) {
            int t = __shfl_up_sync(0xffffffffu, y, off);
            if (lane >= off) y += t;
        }
        wsum[lane] = y;
    }
    __syncthreads();
    if (tid == 0) blockbase = atomicAdd(&g_total, wsum[31]);
    __syncthreads();
    int pre = (wid > 0) ? wsum[wid - 1] : 0;
    if (i < n) g_rowstart[i] = blockbase + pre + x - v;
}

__global__ void edge_fill_k(const int* __restrict__ ei, const float* __restrict__ ew, int E) {
    int e = blockIdx.x * blockDim.x + threadIdx.x;
    if (e >= E) return;
    int r = ei[e];
    int c = ei[E + e];
    int p = g_rowstart[r] + atomicAdd(&g_fill[r], 1);
    float nw = -ew[e] * g_dinv[r] * g_dinv[c];
    g_epack[p] = make_int2(c, __float_as_int(nw));
}

// ---------------------------------------------------------------------------
// Sparse propagation: acc[row] = sum_{edges of row} norm * z[col]
// MODE 0: generic (insel 1: g_Z -> g_T1, insel 2: g_T1 -> g_T2)
// MODE 1 (layer-0 fused): in g_Z (C2), out g_T2[r] = g_T1[r] + 2*acc
// MODE 2 (layer-0 fused): in g_T2, out g_H[r] = softplus(g_H[r]-g_Z[r]+acc+b)
// ---------------------------------------------------------------------------
template<int MODE>
__global__ void prop_k(int insel, int n, int fi4, const float* __restrict__ bias) {
    int row = blockIdx.x * blockDim.y + threadIdx.y;
    if (row >= n) return;
    const float* Zin;
    float* Out;
    if (MODE == 0)      { Zin = (insel == 1) ? g_Z : g_T1; Out = (insel == 1) ? g_T1 : g_T2; }
    else if (MODE == 1) { Zin = g_Z;  Out = g_T2; }
    else                { Zin = g_T2; Out = g_H;  }
    int xf = threadIdx.x;
    int s = g_rowstart[row];
    int e = s + g_cnt[row];
    const float4* Z4 = (const float4*)Zin;
    float ax = 0.f, ay = 0.f, az = 0.f, aw = 0.f;
    int i = s;
    for (; i + 4 <= e; i += 4) {
        int2 e0 = g_epack[i], e1 = g_epack[i+1], e2 = g_epack[i+2], e3 = g_epack[i+3];
        float4 z0 = Z4[e0.x * fi4 + xf];
        float4 z1 = Z4[e1.x * fi4 + xf];
        float4 z2 = Z4[e2.x * fi4 + xf];
        float4 z3 = Z4[e3.x * fi4 + xf];
        float w0 = __int_as_float(e0.y), w1 = __int_as_float(e1.y);
        float w2 = __int_as_float(e2.y), w3 = __int_as_float(e3.y);
        ax = fmaf(w0, z0.x, ax); ay = fmaf(w0, z0.y, ay); az = fmaf(w0, z0.z, az); aw = fmaf(w0, z0.w, aw);
        ax = fmaf(w1, z1.x, ax); ay = fmaf(w1, z1.y, ay); az = fmaf(w1, z1.z, az); aw = fmaf(w1, z1.w, aw);
        ax = fmaf(w2, z2.x, ax); ay = fmaf(w2, z2.y, ay); az = fmaf(w2, z2.z, az); aw = fmaf(w2, z2.w, aw);
        ax = fmaf(w3, z3.x, ax); ay = fmaf(w3, z3.y, ay); az = fmaf(w3, z3.z, az); aw = fmaf(w3, z3.w, aw);
    }
    for (; i < e; i++) {
        int2 ep = g_epack[i];
        float4 z0 = Z4[ep.x * fi4 + xf];
        float w0 = __int_as_float(ep.y);
        ax = fmaf(w0, z0.x, ax); ay = fmaf(w0, z0.y, ay); az = fmaf(w0, z0.z, az); aw = fmaf(w0, z0.w, aw);
    }
    int idx = row * fi4 + xf;
    float4 o;
    if (MODE == 0) {
        o = make_float4(ax, ay, az, aw);
    } else if (MODE == 1) {
        float4 c1 = ((const float4*)g_T1)[idx];
        o = make_float4(c1.x + 2.f*ax, c1.y + 2.f*ay, c1.z + 2.f*az, c1.w + 2.f*aw);
    } else {
        float4 c0 = ((const float4*)g_H)[idx];
        float4 c2 = ((const float4*)g_Z)[idx];
        float4 bb = ((const float4*)bias)[xf];
        o.x = softplus_f(c0.x - c2.x + ax + bb.x);
        o.y = softplus_f(c0.y - c2.y + ay + bb.y);
        o.z = softplus_f(c0.z - c2.z + az + bb.z);
        o.w = softplus_f(c0.w - c2.w + aw + bb.w);
    }
    ((float4*)Out)[idx] = o;
}

// ---------------------------------------------------------------------------
// Layer-0 commuted GEMM: C0 = x@W0 -> g_H, C1 = x@W1 -> g_T1, C2 = x@W2 -> g_Z
// FI=128, per-mat FO=16. f32x2 packed math.
// ---------------------------------------------------------------------------
__global__ void __launch_bounds__(128) cheb_gemm0_k(
    const float* __restrict__ x, const float* __restrict__ W, int n)
{
    constexpr int CG = 4, RPI = 32, RM = 4, BM = RPI * RM;   // BM = 128
    const int cg = threadIdx.x % CG, r0 = threadIdx.x / CG;
    const int rowbase = blockIdx.x * BM;
    const ulonglong2* Wp = (const ulonglong2*)W;   // [3][128][4] of ull2
    const float4* X4 = (const float4*)x;

    ull acc0[RM][2], acc1[RM][2], acc2[RM][2];
    int rows[RM]; bool vld[RM];
#pragma unroll
    for (int r = 0; r < RM; r++) {
        acc0[r][0] = acc0[r][1] = 0ull;
        acc1[r][0] = acc1[r][1] = 0ull;
        acc2[r][0] = acc2[r][1] = 0ull;
        rows[r] = rowbase + r0 + r * RPI;
        vld[r]  = rows[r] < n;
    }

    for (int k0 = 0; k0 < 128; k0 += 4) {
        ulonglong2 w0[4], w1[4], w2[4];
#pragma unroll
        for (int kk = 0; kk < 4; kk++) {
            int wi = (k0 + kk) * CG + cg;
            w0[kk] = Wp[wi];
            w1[kk] = Wp[512 + wi];
            w2[kk] = Wp[1024 + wi];
        }
#pragma unroll
        for (int r = 0; r < RM; r++) {
            float4 z4 = make_float4(0.f, 0.f, 0.f, 0.f);
            if (vld[r]) z4 = X4[rows[r] * 32 + (k0 >> 2)];
            float zz[4] = {z4.x, z4.y, z4.z, z4.w};
#pragma unroll
            for (int kk = 0; kk < 4; kk++) {
                ull a2 = bc2(zz[kk]);
                fma2(acc0[r][0], a2, w0[kk].x); fma2(acc0[r][1], a2, w0[kk].y);
                fma2(acc1[r][0], a2, w1[kk].x); fma2(acc1[r][1], a2, w1[kk].y);
                fma2(acc2[r][0], a2, w2[kk].x); fma2(acc2[r][1], a2, w2[kk].y);
            }
        }
    }

#pragma unroll
    for (int r = 0; r < RM; r++) {
        if (!vld[r]) continue;
        int off = rows[r] * CG + cg;
        F2U l, h;
        l.u = acc0[r][0]; h.u = acc0[r][1];
        ((float4*)g_H )[off] = make_float4(l.f.x, l.f.y, h.f.x, h.f.y);
        l.u = acc1[r][0]; h.u = acc1[r][1];
        ((float4*)g_T1)[off] = make_float4(l.f.x, l.f.y, h.f.x, h.f.y);
        l.u = acc2[r][0]; h.u = acc2[r][1];
        ((float4*)g_Z )[off] = make_float4(l.f.x, l.f.y, h.f.x, h.f.y);
    }
}

// ---------------------------------------------------------------------------
// Standard Chebyshev combine GEMM (layers 1-4), f32x2 packed:
//   H = Z @ W0 + T1 @ W1 + (2*T2raw - Z) @ W2 + b   (+ optional softplus)
// ---------------------------------------------------------------------------
template<int FI, int FO, int RM, int THREADS, bool ACT>
__global__ void __launch_bounds__(THREADS) cheb_gemm2_k(
    const float* __restrict__ W, const float* __restrict__ b, int n)
{
    constexpr int CG = FO / 4;
    constexpr int RPI = THREADS / CG;
    constexpr int BM = RPI * RM;
    const int cg = threadIdx.x % CG, r0 = threadIdx.x / CG;
    const int rowbase = blockIdx.x * BM;
    const ulonglong2* Wp = (const ulonglong2*)W;   // [3][FI][CG] of ull2
    const float4* Z4 = (const float4*)g_Z;
    const float4* A4 = (const float4*)g_T1;
    const float4* P4 = (const float4*)g_T2;

    ulonglong2 bb = ((const ulonglong2*)b)[cg];
    ull acc[RM][2];
    int rows[RM]; bool vld[RM];
#pragma unroll
    for (int r = 0; r < RM; r++) {
        acc[r][0] = bb.x; acc[r][1] = bb.y;
        rows[r] = rowbase + r0 + r * RPI;
        vld[r]  = rows[r] < n;
    }

    for (int k0 = 0; k0 < FI; k0 += 4) {
        ulonglong2 w0[4], w1[4], w2[4];
#pragma unroll
        for (int kk = 0; kk < 4; kk++) {
            int wi = (k0 + kk) * CG + cg;
            w0[kk] = Wp[wi];
            w1[kk] = Wp[FI * CG + wi];
            w2[kk] = Wp[2 * FI * CG + wi];
        }
#pragma unroll
        for (int r = 0; r < RM; r++) {
            float4 z4 = make_float4(0.f, 0.f, 0.f, 0.f);
            float4 a4 = z4, p4 = z4;
            if (vld[r]) {
                int off = rows[r] * (FI / 4) + (k0 >> 2);
                z4 = Z4[off]; a4 = A4[off]; p4 = P4[off];
            }
            float zz[4] = {z4.x, z4.y, z4.z, z4.w};
            float tt[4] = {a4.x, a4.y, a4.z, a4.w};
            float uu[4] = {2.f*p4.x - z4.x, 2.f*p4.y - z4.y, 2.f*p4.z - z4.z, 2.f*p4.w - z4.w};
#pragma unroll
            for (int kk = 0; kk < 4; kk++) {
                ull a2 = bc2(zz[kk]);
                fma2(acc[r][0], a2, w0[kk].x); fma2(acc[r][1], a2, w0[kk].y);
                ull t2 = bc2(tt[kk]);
                fma2(acc[r][0], t2, w1[kk].x); fma2(acc[r][1], t2, w1[kk].y);
                ull u2 = bc2(uu[kk]);
                fma2(acc[r][0], u2, w2[kk].x); fma2(acc[r][1], u2, w2[kk].y);
            }
        }
    }

#pragma unroll
    for (int r = 0; r < RM; r++) {
        if (!vld[r]) continue;
        F2U l, h; l.u = acc[r][0]; h.u = acc[r][1];
        float4 o = make_float4(l.f.x, l.f.y, h.f.x, h.f.y);
        if (ACT) {
            o.x = softplus_f(o.x); o.y = softplus_f(o.y);
            o.z = softplus_f(o.z); o.w = softplus_f(o.w);
        }
        ((float4*)g_H)[rows[r] * CG + cg] = o;
    }
}

// ---------------------------------------------------------------------------
// BatchNorm (training-mode, biased variance)
// ---------------------------------------------------------------------------
__global__ void bn_stats_k(int n, int fo) {
    int tid = threadIdx.x;
    int f = tid % fo;
    int copy = tid / fo;
    int copies = 256 / fo;
    float s = 0.f, q = 0.f;
    for (int row = blockIdx.x * copies + copy; row < n; row += gridDim.x * copies) {
        float v = g_H[row * fo + f];
        s += v; q = fmaf(v, v, q);
    }
    __shared__ float sh[256], sh2[256];
    sh[tid] = s; sh2[tid] = q;
    __syncthreads();
    for (int off = 128; off >= fo; off >>= 1) {
        if (tid < off) { sh[tid] += sh[tid + off]; sh2[tid] += sh2[tid + off]; }
        __syncthreads();
    }
    if (tid < fo) {
        atomicAdd(&g_bnsum[tid], sh[tid]);
        atomicAdd(&g_bnsq [tid], sh2[tid]);
    }
}

__global__ void bn_finalize_k(const float* __restrict__ gma, const float* __restrict__ beta,
                              int n, int fo) {
    int f = threadIdx.x;
    if (f < fo) {
        float inv_n = 1.f / (float)n;
        float m = g_bnsum[f] * inv_n;
        float v = g_bnsq[f] * inv_n - m * m;
        float sc = gma[f] * rsqrtf(fmaxf(v, 0.f) + 1e-5f);
        g_scale[f] = sc;
        g_shift[f] = beta[f] - m * sc;
    }
    // reset accumulators for the next layer / next call
    g_bnsum[f] = 0.f; g_bnsq[f] = 0.f;
}

__global__ void bn_apply_k(int total4, int fo4) {
    for (int i = blockIdx.x * blockDim.x + threadIdx.x; i < total4;
         i += gridDim.x * blockDim.x) {
        float4 h  = ((const float4*)g_H)[i];
        int f4 = i % fo4;
        float4 sc = ((const float4*)g_scale)[f4];
        float4 sh = ((const float4*)g_shift)[f4];
        float4 o;
        o.x = fmaf(h.x, sc.x, sh.x);
        o.y = fmaf(h.y, sc.y, sh.y);
        o.z = fmaf(h.z, sc.z, sh.z);
        o.w = fmaf(h.w, sc.w, sh.w);
        ((float4*)g_Z)[i] = o;
    }
}

// ---------------------------------------------------------------------------
// Pooling + dense head
// ---------------------------------------------------------------------------
__global__ void pool_setup_k(const int* __restrict__ batch, int n, int G) {
    int i = blockIdx.x * blockDim.x + threadIdx.x;
    if (i < G * 256) { g_poolmax[i] = INT_MIN; g_poolsum[i] = 0.f; }
    if (i <= G) {
        if (i == G) { g_segstart[G] = n; }
        else {
            int lo = 0, hi = n;
            while (lo < hi) {
                int mid = (lo + hi) >> 1;
                if (batch[mid] < i) lo = mid + 1; else hi = mid;
            }
            g_segstart[i] = lo;
        }
    }
}

#define POOL_ROWS 128
__global__ void pool_k(const int* __restrict__ batch, int n) {
    int f  = threadIdx.x;               // 256 features
    int rs = blockIdx.x * POOL_ROWS;
    if (rs >= n) return;
    int re = min(rs + POOL_ROWS, n);
    int cur = batch[rs];
    float mx = -FLT_MAX, sm = 0.f;
    for (int r = rs; r < re; r++) {
        int g = batch[r];
        if (g != cur) {
            atomicMax(&g_poolmax[cur * 256 + f], fmap_f(mx));
            atomicAdd(&g_poolsum[cur * 256 + f], sm);
            cur = g; mx = -FLT_MAX; sm = 0.f;
        }
        float v = g_H[r * 256 + f];
        mx = fmaxf(mx, v); sm += v;
    }
    atomicMax(&g_poolmax[cur * 256 + f], fmap_f(mx));
    atomicAdd(&g_poolsum[cur * 256 + f], sm);
}

__global__ void dense_k(const float* __restrict__ Wd, const float* __restrict__ bd,
                        float* __restrict__ out) {
    __shared__ float sh[4][128];
    int g = blockIdx.x, tid = threadIdx.x;
    int s = g_segstart[g], e = g_segstart[g + 1];
    float cnt = fmaxf((float)(e - s), 1.f);
    float a[4] = {0.f, 0.f, 0.f, 0.f};
    for (int k = tid; k < 512; k += 128) {
        float pv;
        if (k < 256) {
            int key = g_poolmax[g * 256 + k];
            pv = (key == INT_MIN) ? 0.f : funmap_f(key);
        } else {
            pv = g_poolsum[g * 256 + (k - 256)] / cnt;
        }
#pragma unroll
        for (int j = 0; j < 4; j++) a[j] = fmaf(pv, Wd[k * 4 + j], a[j]);
    }
#pragma unroll
    for (int j = 0; j < 4; j++) sh[j][tid] = a[j];
    __syncthreads();
    for (int off = 64; off >= 1; off >>= 1) {
        if (tid < off) {
#pragma unroll
            for (int j = 0; j < 4; j++) sh[j][tid] += sh[j][tid + off];
        }
        __syncthreads();
    }
    if (tid == 0) {
        float l[4];
#pragma unroll
        for (int j = 0; j < 4; j++) l[j] = sh[j][0] + bd[j];
        float m = fmaxf(fmaxf(l[0], l[1]), fmaxf(l[2], l[3]));
        float se = 0.f;
#pragma unroll
        for (int j = 0; j < 4; j++) se += expf(l[j] - m);
        float lse = m + logf(se);
#pragma unroll
        for (int j = 0; j < 4; j++) out[g * 4 + j] = l[j] - lse;
    }
}

// ---------------------------------------------------------------------------
// Host launcher
// ---------------------------------------------------------------------------
static inline void launch_prop0(int n, int fi4, int insel) {
    dim3 blk(fi4, 256 / fi4);
    int grd = (n + blk.y - 1) / blk.y;
    prop_k<0><<<grd, blk>>>(insel, n, fi4, nullptr);
}

extern "C" void kernel_launch(void* const* d_in, const int* in_sizes, int n_in,
                              void* d_out, int out_size) {
    const float *x, *ew, *W[5], *b[5], *gm[4], *be[4], *Wd, *bd;
    const int *ei, *bi;

    bool setup_order = (in_sizes[2] > 1000000);
    if (setup_order) {
        x  = (const float*)d_in[0];
        ew = (const float*)d_in[1];
        ei = (const int*)  d_in[2];
        bi = (const int*)  d_in[3];
        int p = 4;
        for (int l = 0; l < 5; l++) {
            W[l] = (const float*)d_in[p++];
            b[l] = (const float*)d_in[p++];
            if (l < 4) { gm[l] = (const float*)d_in[p++]; be[l] = (const float*)d_in[p++]; }
        }
        Wd = (const float*)d_in[p++];
        bd = (const float*)d_in[p++];
    } else {
        x  = (const float*)d_in[0];
        ew = (const float*)d_in[1];
        int p = 2;
        for (int l = 0; l < 5; l++) {
            W[l] = (const float*)d_in[p++];
            b[l] = (const float*)d_in[p++];
            if (l < 4) { gm[l] = (const float*)d_in[p++]; be[l] = (const float*)d_in[p++]; }
        }
        Wd = (const float*)d_in[p++];
        bd = (const float*)d_in[p++];
        ei = (const int*)d_in[p++];
        bi = (const int*)d_in[p++];
    }

    const int n = in_sizes[0] / 128;
    const int E = in_sizes[1];
    const int G = out_size / 4;     // 64
    float* out = (float*)d_out;

    // ---- preprocessing: degrees, dinv, CSR build ----
    zero_init_k<<<(n + 255) / 256, 256>>>(n);
    edge_deg_k<<<(E + 255) / 256, 256>>>(ei, ew, E);
    dinv_k<<<(n + 255) / 256, 256>>>(n);
    rowbase_k<<<(n + 1023) / 1024, 1024>>>(n);
    edge_fill_k<<<(E + 255) / 256, 256>>>(ei, ew, E);

    // ---- Layer 0 (commuted: GEMM first, props at width 16) ----
    cheb_gemm0_k<<<(n + 127) / 128, 128>>>(x, W[0], n);
    {
        dim3 blk(4, 64);
        int grd = (n + 63) / 64;
        prop_k<1><<<grd, blk>>>(0, n, 4, nullptr);   // T = C1 + 2 * L C2  -> g_T2
        prop_k<2><<<grd, blk>>>(0, n, 4, b[0]);      // H = sp(C0 - C2 + L T + b)
    }
    // BN after layer 0 (fo = 16)
    bn_stats_k<<<256, 256>>>(n, 16);
    bn_finalize_k<<<1, 256>>>(gm[0], be[0], n, 16);
    {
        int total4 = n * 16 / 4;
        int agrid = (total4 + 255) / 256; if (agrid > 2048) agrid = 2048;
        bn_apply_k<<<agrid, 256>>>(total4, 4);
    }

    // ---- Layers 1-4 (standard form: props at width fi, then combine GEMM) ----
    const int fi4_arr[5] = {0, 4, 8, 16, 32};   // fi/4 for layers 1..4
    const int fo_arr[5]  = {16, 32, 64, 128, 256};
    for (int l = 1; l < 5; l++) {
        int fi4 = fi4_arr[l];
        launch_prop0(n, fi4, 1);   // T1 = L Z
        launch_prop0(n, fi4, 2);   // T2raw = L T1

        switch (l) {
            case 1: cheb_gemm2_k< 16,  32, 4, 128, true ><<<(n + 63) / 64, 128>>>(W[1], b[1], n); break;
            case 2: cheb_gemm2_k< 32,  64, 8, 128, true ><<<(n + 63) / 64, 128>>>(W[2], b[2], n); break;
            case 3: cheb_gemm2_k< 64, 128, 8, 256, true ><<<(n + 63) / 64, 256>>>(W[3], b[3], n); break;
            case 4: cheb_gemm2_k<128, 256, 8, 512, false><<<(n + 63) / 64, 512>>>(W[4], b[4], n); break;
        }

        if (l < 4) {
            int FO = fo_arr[l];
            bn_stats_k<<<256, 256>>>(n, FO);
            bn_finalize_k<<<1, 256>>>(gm[l], be[l], n, FO);
            int total4 = n * FO / 4;
            int agrid = (total4 + 255) / 256; if (agrid > 2048) agrid = 2048;
            bn_apply_k<<<agrid, 256>>>(total4, FO / 4);
        }
    }

    // ---- pooling + dense head ----
    pool_setup_k<<<(G * 256 + 255) / 256, 256>>>(bi, n, G);
    pool_k<<<(n + POOL_ROWS - 1) / POOL_ROWS, 256>>>(bi, n);
    dense_k<<<G, 128>>>(Wd, bd, out);
}